// round 11
// baseline (speedup 1.0000x reference)
#include <cuda_runtime.h>
#include <math.h>

// Problem constants (fixed by the dataset)
#define NB        8          // batch
#define C_IN      4
#define N_ETYPE   5
#define N_NTYPE   7
#define C_OUT     32
#define TEMB_CH   512
#define FAN       55         // N_ETYPE * (C_IN + N_NTYPE)
#define NMAX      400000

// Scatter accumulators:
//   g_xsum[node][et][4] : float x-sums (red.v4.f32 target)        32 MB
//   g_cnt [node][et][2] : 7 x 8-bit counters per bucket (u32 red) 16 MB
// Zero at load; gemv re-zeros what it consumes (replay invariant).
__device__ float    g_xsum[NMAX * N_ETYPE * 4];
__device__ unsigned g_cnt [NMAX * N_ETYPE * 2];
// Packed gather row: [x0,x1,x2,x3, nt(int), pad, pad, pad] = 32 B/node.
__device__ float    g_xa  [NMAX * 8];             // 12.8 MB
__device__ float    g_l2  [NB * TEMB_CH];         // lin2 pre-activation accum
__device__ float    g_inj [NB * C_OUT];

// ---------------------------------------------------------------------------
// Fused kernel A v2: blocks [0,64) = (kseg, col_tile) compute lin1+lin2
// partials for ALL 8 batches from ONE W2 slice (W2 read exactly once chip-
// wide); partials land in g_l2 via atomicAdd (zeroed by inj consumer).
// Blocks [64, ...) pack the per-node gather row g_xa.
// Thread layout inside temb blocks: tid = b*64 + j  (b: batch, j: col/lane).
// ---------------------------------------------------------------------------
__global__ void fusedA_kernel(const float* __restrict__ t,
                              const float* __restrict__ W1,
                              const float* __restrict__ b1,
                              const float* __restrict__ W2,
                              const float* __restrict__ x,
                              const int* __restrict__ ntype, int N) {
    const int tid = threadIdx.x;
    if (blockIdx.x >= 64) {
        int n = (blockIdx.x - 64) * 512 + tid;
        if (n < N) {
            float4 xv = *reinterpret_cast<const float4*>(x + (size_t)n * C_IN);
            float* row = g_xa + (size_t)n * 8;
            *reinterpret_cast<float4*>(row) = xv;
            reinterpret_cast<int*>(row)[4] = ntype[n];
        }
        return;
    }

    __shared__ float emb[NB][128];
    __shared__ float h1s[NB][64];
    const int ks = blockIdx.x >> 3;      // K segment of lin2 (h1 slice)
    const int bo = blockIdx.x & 7;       // output column tile of lin2
    const int b  = tid >> 6;             // batch
    const int j  = tid & 63;             // lane within 64

    {   // sinusoidal embedding, all batches
        float f = expf(-(float)j * (logf(10000.0f) / 63.0f));
        float ang = t[b] * f;
        emb[b][j]      = sinf(ang);
        emb[b][j + 64] = cosf(ang);
    }
    __syncthreads();

    {   // h1 slice [ks*64, ks*64+64) for all batches
        float s = b1[ks * 64 + j];
        const float* w = W1 + ks * 64 + j;
        #pragma unroll 8
        for (int i = 0; i < 128; i++) s += emb[b][i] * w[(size_t)i * TEMB_CH];
        h1s[b][j] = s * (1.0f / (1.0f + expf(-s)));
    }
    __syncthreads();

    {   // lin2 partial: column bo*64+j, K in [ks*64, ks*64+64)
        float s = 0.0f;
        const float* w = W2 + (size_t)(ks * 64) * TEMB_CH + bo * 64 + j;
        #pragma unroll 8
        for (int k = 0; k < 64; k++) s += h1s[b][k] * w[(size_t)k * TEMB_CH];
        atomicAdd(g_l2 + b * TEMB_CH + bo * 64 + j, s);
    }
}

// ---------------------------------------------------------------------------
// Fused kernel B: blocks [0,8) compute inj = swish(l2 + b2) @ W_temb and
// restore g_l2's zero-invariant; blocks [8,...) scatter edges (2/thread).
// ---------------------------------------------------------------------------
__global__ void scatterB_kernel(const int* __restrict__ ei,
                                const int* __restrict__ etype,
                                const float* __restrict__ b2,
                                const float* __restrict__ Wt,
                                int E) {
    const int tid = threadIdx.x;
    if (blockIdx.x < 8) {
        __shared__ float sws[TEMB_CH];
        __shared__ float part[8][33];
        const int b = blockIdx.x;

        for (int i = tid; i < TEMB_CH; i += 256) {
            float v = g_l2[b * TEMB_CH + i] + b2[i];
            sws[i] = v * (1.0f / (1.0f + expf(-v)));
        }
        __syncthreads();
        for (int i = tid; i < TEMB_CH; i += 256)   // restore zero-invariant
            g_l2[b * TEMB_CH + i] = 0.0f;

        const int c  = tid & 31;
        const int ks = tid >> 5;
        const float* sw = sws + ks * 64;
        const float* w  = Wt + (ks * 64) * C_OUT + c;
        float s = 0.0f;
        #pragma unroll 8
        for (int i = 0; i < 64; i++) s += sw[i] * w[i * C_OUT];
        part[ks][c] = s;
        __syncthreads();

        if (tid < 32) {
            float v = 0.0f;
            #pragma unroll
            for (int k = 0; k < 8; k++) v += part[k][tid];
            g_inj[b * C_OUT + tid] = v;
        }
        return;
    }

    int e2 = ((blockIdx.x - 8) * blockDim.x + tid) * 2;
    if (e2 >= E) return;
    int2 rows = *reinterpret_cast<const int2*>(ei + e2);
    int2 cols = *reinterpret_cast<const int2*>(ei + E + e2);
    int2 ets  = *reinterpret_cast<const int2*>(etype + e2);

    const float* r0 = g_xa + (size_t)cols.x * 8;
    const float* r1 = g_xa + (size_t)cols.y * 8;
    float4 xv0 = *reinterpret_cast<const float4*>(r0);
    float4 xv1 = *reinterpret_cast<const float4*>(r1);
    int nt0 = reinterpret_cast<const int*>(r0)[4];
    int nt1 = reinterpret_cast<const int*>(r1)[4];

    size_t bk0 = (size_t)rows.x * N_ETYPE + ets.x;
    size_t bk1 = (size_t)rows.y * N_ETYPE + ets.y;

    asm volatile("red.global.add.v4.f32 [%0], {%1,%2,%3,%4};"
                 :: "l"(g_xsum + bk0 * 4), "f"(xv0.x), "f"(xv0.y), "f"(xv0.z), "f"(xv0.w)
                 : "memory");
    asm volatile("red.global.add.v4.f32 [%0], {%1,%2,%3,%4};"
                 :: "l"(g_xsum + bk1 * 4), "f"(xv1.x), "f"(xv1.y), "f"(xv1.z), "f"(xv1.w)
                 : "memory");
    atomicAdd(g_cnt + bk0 * 2 + (nt0 >> 2), 1u << ((nt0 & 3) * 8));
    atomicAdd(g_cnt + bk1 * 2 + (nt1 >> 2), 1u << ((nt1 & 3) * 8));
}

// ---------------------------------------------------------------------------
// u8 counter -> exact fp32 via PRMT magic number (no I2F, no mask chains).
// ---------------------------------------------------------------------------
template <int K>
__device__ __forceinline__ float byte2f(unsigned w) {
    unsigned r;
    asm("prmt.b32 %0, %1, %2, %3;"
        : "=r"(r) : "r"(w), "r"(0x4B000000u), "n"(0x7540u | K));
    return __uint_as_float(r) - 8388608.0f;
}

// ---------------------------------------------------------------------------
// Per-node GEMV v7b: ONE node per thread; ALL global loads hoisted (MLP~9,
// one latency exposure); counters via 8-byte uint2 ops ONLY (40B/node stride
// is 8B-aligned for every n -- the uint4 variant faulted on odd n).
// ---------------------------------------------------------------------------
__global__ void __launch_bounds__(256, 3)
gemv_kernel(const float* __restrict__ Wc,
            const int* __restrict__ batch_id,
            float* __restrict__ out,
            int N) {
    __shared__ __align__(16) float Ws[FAN * C_OUT];   // pre-scaled by 0.2
    __shared__ float injs[NB * 33];
    const int tid = threadIdx.x;
    for (int i = tid; i < FAN * C_OUT; i += blockDim.x) Ws[i] = Wc[i] * 0.2f;
    if (tid < NB * C_OUT) {
        int b = tid >> 5, c = tid & 31;
        injs[b * 33 + c] = g_inj[tid];
    }
    __syncthreads();

    int n = blockIdx.x * blockDim.x + tid;
    if (n >= N) return;

    float*    xp = g_xsum + (size_t)n * (N_ETYPE * 4);   // 80B stride: 16B-aligned
    unsigned* cp = g_cnt  + (size_t)n * (N_ETYPE * 2);   // 40B stride: 8B-aligned

    // Hoist ALL global loads: 5x LDG.128 + 5x LDG.64 + batch id.
    float4 xv0 = *reinterpret_cast<float4*>(xp + 0);
    float4 xv1 = *reinterpret_cast<float4*>(xp + 4);
    float4 xv2 = *reinterpret_cast<float4*>(xp + 8);
    float4 xv3 = *reinterpret_cast<float4*>(xp + 12);
    float4 xv4 = *reinterpret_cast<float4*>(xp + 16);
    uint2  c0  = *reinterpret_cast<uint2*>(cp + 0);
    uint2  c1  = *reinterpret_cast<uint2*>(cp + 2);
    uint2  c2  = *reinterpret_cast<uint2*>(cp + 4);
    uint2  c3  = *reinterpret_cast<uint2*>(cp + 6);
    uint2  c4  = *reinterpret_cast<uint2*>(cp + 8);
    int    bb  = batch_id[n];

    unsigned long long acc[16];
    #pragma unroll
    for (int k = 0; k < 16; k++) acc[k] = 0ULL;

    const float4 xvs[5] = {xv0, xv1, xv2, xv3, xv4};
    const uint2  cws[5] = {c0, c1, c2, c3, c4};

    #pragma unroll
    for (int et = 0; et < N_ETYPE; et++) {
        unsigned lo = cws[et].x, hi = cws[et].y;
        float a[11];
        a[0] = xvs[et].x; a[1] = xvs[et].y; a[2] = xvs[et].z; a[3] = xvs[et].w;
        a[4] = byte2f<0>(lo); a[5] = byte2f<1>(lo);
        a[6] = byte2f<2>(lo); a[7] = byte2f<3>(lo);
        a[8] = byte2f<0>(hi); a[9] = byte2f<1>(hi);
        a[10] = byte2f<2>(hi);

        #pragma unroll
        for (int j = 0; j < 11; j++) {
            const ulonglong2* Wv =
                reinterpret_cast<const ulonglong2*>(&Ws[(et * 11 + j) * C_OUT]);
            unsigned long long av;
            asm("mov.b64 %0, {%1, %1};" : "=l"(av) : "f"(a[j]));
            #pragma unroll
            for (int q = 0; q < 8; q++) {
                ulonglong2 w = Wv[q];               // one LDS.128, two u64 operands
                asm("fma.rn.f32x2 %0, %1, %2, %0;"
                    : "+l"(acc[2 * q + 0]) : "l"(av), "l"(w.x));
                asm("fma.rn.f32x2 %0, %1, %2, %0;"
                    : "+l"(acc[2 * q + 1]) : "l"(av), "l"(w.y));
            }
        }
    }

    const float* iv = &injs[bb * 33];
    float* op = out + (size_t)n * C_OUT;
    #pragma unroll
    for (int k = 0; k < 16; k += 2) {
        float l0, h0, l1, h1;
        asm("mov.b64 {%0, %1}, %2;" : "=f"(l0), "=f"(h0) : "l"(acc[k]));
        asm("mov.b64 {%0, %1}, %2;" : "=f"(l1), "=f"(h1) : "l"(acc[k + 1]));
        float4 o; o.x = l0 + iv[2*k]; o.y = h0 + iv[2*k+1];
        o.z = l1 + iv[2*k+2]; o.w = h1 + iv[2*k+3];
        *reinterpret_cast<float4*>(op + 2 * k) = o;
    }

    // Re-zero this node's accumulators (16B stores for xsum, 8B for counts).
    float4 z4 = make_float4(0.f, 0.f, 0.f, 0.f);
    #pragma unroll
    for (int i = 0; i < N_ETYPE; i++)
        *reinterpret_cast<float4*>(xp + i * 4) = z4;
    uint2 z2 = make_uint2(0u, 0u);
    #pragma unroll
    for (int i = 0; i < N_ETYPE; i++)
        *reinterpret_cast<uint2*>(cp + i * 2) = z2;
}

// ---------------------------------------------------------------------------
// Inputs (metadata order):
//  0 x [N,4] f32        1 t [8] f32          2 edge_index [2,E] i32
//  3 edge_type [E] i32  4 node_type [N] i32  5 batch_id [N] i32
//  6 W_conv [55,32] f32 7 W1 [128,512]       8 b1 [512]
//  9 W2 [512,512]      10 b2 [512]          11 W_temb [512,32]
// Output: [N,32] f32
// ---------------------------------------------------------------------------
extern "C" void kernel_launch(void* const* d_in, const int* in_sizes, int n_in,
                              void* d_out, int out_size) {
    const float* x        = (const float*)d_in[0];
    const float* t        = (const float*)d_in[1];
    const int*   ei       = (const int*)d_in[2];
    const int*   etype    = (const int*)d_in[3];
    const int*   ntype    = (const int*)d_in[4];
    const int*   batch_id = (const int*)d_in[5];
    const float* W_conv   = (const float*)d_in[6];
    const float* W1       = (const float*)d_in[7];
    const float* b1       = (const float*)d_in[8];
    const float* W2       = (const float*)d_in[9];
    const float* b2       = (const float*)d_in[10];
    const float* W_temb   = (const float*)d_in[11];
    float* out = (float*)d_out;

    const int E = in_sizes[3];
    const int N = in_sizes[4];
    const int prep_blocks = (N + 511) / 512;
    const int edge_blocks = (E / 2 + 255) / 256;

    fusedA_kernel<<<64 + prep_blocks, 512>>>(t, W1, b1, W2, x, ntype, N);
    scatterB_kernel<<<8 + edge_blocks, 256>>>(ei, etype, b2, W_temb, E);
    gemv_kernel<<<(N + 255) / 256, 256>>>(W_conv, batch_id, out, N);
}

// round 12
// speedup vs baseline: 1.2888x; 1.2888x over previous
#include <cuda_runtime.h>
#include <math.h>

// Problem constants (fixed by the dataset)
#define NB        8          // batch
#define C_IN      4
#define N_ETYPE   5
#define N_NTYPE   7
#define C_OUT     32
#define TEMB_CH   512
#define FAN       55         // N_ETYPE * (C_IN + N_NTYPE)
#define NMAX      400000

// Scatter accumulators (zero at load; gemv re-zeros what it consumes):
__device__ float    g_xsum[NMAX * N_ETYPE * 4];   // 32 MB
__device__ unsigned g_cnt [NMAX * N_ETYPE * 2];   // 16 MB
__device__ float    g_l2  [NB * TEMB_CH];         // lin2 pre-activation accum
__device__ float    g_inj [NB * C_OUT];
__device__ int      g_done0;                      // temb-block arrivals
__device__ int      g_done1;                      // inj-block arrivals

// ---------------------------------------------------------------------------
// MEGA kernel, 512 threads/block:
//  blocks [0,64)   : temb lin1+lin2 partials -> g_l2 (atomicAdd), signal done0
//  blocks [64,72)  : spin on done0==64, then inj = swish(l2+b2) @ Wt -> g_inj,
//                    re-zero g_l2, self-reset counters for graph replay
//  blocks [72,...) : edge scatter, 2 edges/thread, direct x/ntype gather
// Safe: blocks 0-63 are scheduled in wave 1 before blocks 64-71 (modular CLC /
// LUT placement both respect low-bid-first start), so the spin cannot deadlock.
// ---------------------------------------------------------------------------
__global__ void __launch_bounds__(512)
mega_kernel(const float* __restrict__ t,
            const float* __restrict__ W1,
            const float* __restrict__ b1,
            const float* __restrict__ W2,
            const float* __restrict__ b2,
            const float* __restrict__ Wt,
            const int* __restrict__ ei,
            const int* __restrict__ etype,
            const int* __restrict__ ntype,
            const float* __restrict__ x,
            int E) {
    const int tid = threadIdx.x;

    if (blockIdx.x < 64) {
        // ---- temb: (kseg, col_tile) computes lin1+lin2 for all 8 batches ----
        __shared__ float emb[NB][128];
        __shared__ float h1s[NB][64];
        const int ks = blockIdx.x >> 3;
        const int bo = blockIdx.x & 7;
        const int b  = tid >> 6;
        const int j  = tid & 63;

        {
            float f = expf(-(float)j * (logf(10000.0f) / 63.0f));
            float ang = t[b] * f;
            emb[b][j]      = sinf(ang);
            emb[b][j + 64] = cosf(ang);
        }
        __syncthreads();
        {
            float s = b1[ks * 64 + j];
            const float* w = W1 + ks * 64 + j;
            #pragma unroll 8
            for (int i = 0; i < 128; i++) s += emb[b][i] * w[(size_t)i * TEMB_CH];
            h1s[b][j] = s * (1.0f / (1.0f + expf(-s)));
        }
        __syncthreads();
        {
            float s = 0.0f;
            const float* w = W2 + (size_t)(ks * 64) * TEMB_CH + bo * 64 + j;
            #pragma unroll 8
            for (int k = 0; k < 64; k++) s += h1s[b][k] * w[(size_t)k * TEMB_CH];
            atomicAdd(g_l2 + b * TEMB_CH + bo * 64 + j, s);
        }
        __syncthreads();
        if (tid == 0) {
            __threadfence();
            atomicAdd(&g_done0, 1);
        }
        return;
    }

    if (blockIdx.x < 72) {
        // ---- inj: wait for all temb partials, then project to node channels ----
        __shared__ float sws[TEMB_CH];
        __shared__ float part[16][33];
        const int b = blockIdx.x - 64;

        if (tid == 0) {
            while (atomicAdd(&g_done0, 0) < 64) __nanosleep(200);
            __threadfence();
        }
        __syncthreads();

        for (int i = tid; i < TEMB_CH; i += 512) {
            float v = __ldcg(g_l2 + b * TEMB_CH + i) + b2[i];
            sws[i] = v * (1.0f / (1.0f + expf(-v)));
        }
        __syncthreads();
        for (int i = tid; i < TEMB_CH; i += 512)   // restore zero-invariant
            g_l2[b * TEMB_CH + i] = 0.0f;

        const int c  = tid & 31;
        const int ks = tid >> 5;                   // 0..15
        const float* sw = sws + ks * 32;
        const float* w  = Wt + (ks * 32) * C_OUT + c;
        float s = 0.0f;
        #pragma unroll 8
        for (int i = 0; i < 32; i++) s += sw[i] * w[i * C_OUT];
        part[ks][c] = s;
        __syncthreads();

        if (tid < 32) {
            float v = 0.0f;
            #pragma unroll
            for (int k = 0; k < 16; k++) v += part[k][tid];
            g_inj[b * C_OUT + tid] = v;
        }
        __syncthreads();
        if (tid == 0) {
            __threadfence();
            int r = atomicAdd(&g_done1, 1);
            if (r == 7) {                 // last inj block resets both counters
                atomicExch(&g_done0, 0);
                atomicExch(&g_done1, 0);
            }
        }
        return;
    }

    // ---- edge scatter: 2 edges per thread ----
    int e2 = ((blockIdx.x - 72) * blockDim.x + tid) * 2;
    if (e2 >= E) return;
    int2 rows = *reinterpret_cast<const int2*>(ei + e2);
    int2 cols = *reinterpret_cast<const int2*>(ei + E + e2);
    int2 ets  = *reinterpret_cast<const int2*>(etype + e2);

    int nt0 = __ldg(ntype + cols.x);
    int nt1 = __ldg(ntype + cols.y);
    float4 xv0 = *reinterpret_cast<const float4*>(x + (size_t)cols.x * C_IN);
    float4 xv1 = *reinterpret_cast<const float4*>(x + (size_t)cols.y * C_IN);

    size_t bk0 = (size_t)rows.x * N_ETYPE + ets.x;
    size_t bk1 = (size_t)rows.y * N_ETYPE + ets.y;

    asm volatile("red.global.add.v4.f32 [%0], {%1,%2,%3,%4};"
                 :: "l"(g_xsum + bk0 * 4), "f"(xv0.x), "f"(xv0.y), "f"(xv0.z), "f"(xv0.w)
                 : "memory");
    asm volatile("red.global.add.v4.f32 [%0], {%1,%2,%3,%4};"
                 :: "l"(g_xsum + bk1 * 4), "f"(xv1.x), "f"(xv1.y), "f"(xv1.z), "f"(xv1.w)
                 : "memory");
    atomicAdd(g_cnt + bk0 * 2 + (nt0 >> 2), 1u << ((nt0 & 3) * 8));
    atomicAdd(g_cnt + bk1 * 2 + (nt1 >> 2), 1u << ((nt1 & 3) * 8));
}

// ---------------------------------------------------------------------------
// u8 counter -> exact fp32 via PRMT magic number (no I2F, no mask chains).
// ---------------------------------------------------------------------------
template <int K>
__device__ __forceinline__ float byte2f(unsigned w) {
    unsigned r;
    asm("prmt.b32 %0, %1, %2, %3;"
        : "=r"(r) : "r"(w), "r"(0x4B000000u), "n"(0x7540u | K));
    return __uint_as_float(r) - 8388608.0f;
}

// ---------------------------------------------------------------------------
// GEMV v8: 2 nodes/thread (n0 even -> all vector accesses aligned), ALL
// global loads hoisted to one MLP~9 batch, ulonglong2 smem weights, PRMT
// count conversion, STREAMING (evict-first) stores for `out` so the output
// stream does not evict the L2-resident agg working set.
// ---------------------------------------------------------------------------
__global__ void __launch_bounds__(128, 4)
gemv_kernel(const float* __restrict__ Wc,
            const int* __restrict__ batch_id,
            float* __restrict__ out,
            int N) {
    __shared__ __align__(16) float Ws[FAN * C_OUT];   // pre-scaled by 0.2
    __shared__ float injs[NB * 33];
    const int tid = threadIdx.x;
    for (int i = tid; i < FAN * C_OUT; i += blockDim.x) Ws[i] = Wc[i] * 0.2f;
    for (int i = tid; i < NB * C_OUT; i += blockDim.x) {
        int b = i >> 5, c = i & 31;
        injs[b * 33 + c] = g_inj[i];
    }
    __syncthreads();

    int n0 = (blockIdx.x * blockDim.x + tid) * 2;
    if (n0 >= N) return;

    float*    xp = g_xsum + (size_t)n0 * (N_ETYPE * 4);   // 160B/thread, 16B-aligned
    unsigned* cp = g_cnt  + (size_t)n0 * (N_ETYPE * 2);   // 80B/thread, 16B-aligned

    // Hoist ALL global loads (10x LDG.128 + 2x LDG.128 + 1x LDG.64 + int2).
    float4 xv[10];
    #pragma unroll
    for (int i = 0; i < 10; i++)
        xv[i] = *reinterpret_cast<float4*>(xp + i * 4);
    uint4 ca0 = *reinterpret_cast<uint4*>(cp);
    uint4 ca1 = *reinterpret_cast<uint4*>(cp + 4);
    uint2 ca2 = *reinterpret_cast<uint2*>(cp + 8);
    uint4 cb0 = *reinterpret_cast<uint4*>(cp + 10);
    uint4 cb1 = *reinterpret_cast<uint4*>(cp + 14);
    uint2 cb2 = *reinterpret_cast<uint2*>(cp + 18);
    int2  bb  = *reinterpret_cast<const int2*>(batch_id + n0);

    const unsigned cA[10] = {ca0.x, ca0.y, ca0.z, ca0.w, ca1.x, ca1.y, ca1.z, ca1.w, ca2.x, ca2.y};
    const unsigned cB[10] = {cb0.x, cb0.y, cb0.z, cb0.w, cb1.x, cb1.y, cb1.z, cb1.w, cb2.x, cb2.y};

    unsigned long long acc0[16], acc1[16];
    #pragma unroll
    for (int k = 0; k < 16; k++) { acc0[k] = 0ULL; acc1[k] = 0ULL; }

    #pragma unroll
    for (int et = 0; et < N_ETYPE; et++) {
        float4 v0 = xv[et];
        float4 v1 = xv[N_ETYPE + et];
        unsigned lo0 = cA[et * 2], hi0 = cA[et * 2 + 1];
        unsigned lo1 = cB[et * 2], hi1 = cB[et * 2 + 1];
        float a0[11], a1[11];
        a0[0] = v0.x; a0[1] = v0.y; a0[2] = v0.z; a0[3] = v0.w;
        a0[4] = byte2f<0>(lo0); a0[5] = byte2f<1>(lo0);
        a0[6] = byte2f<2>(lo0); a0[7] = byte2f<3>(lo0);
        a0[8] = byte2f<0>(hi0); a0[9] = byte2f<1>(hi0);
        a0[10] = byte2f<2>(hi0);
        a1[0] = v1.x; a1[1] = v1.y; a1[2] = v1.z; a1[3] = v1.w;
        a1[4] = byte2f<0>(lo1); a1[5] = byte2f<1>(lo1);
        a1[6] = byte2f<2>(lo1); a1[7] = byte2f<3>(lo1);
        a1[8] = byte2f<0>(hi1); a1[9] = byte2f<1>(hi1);
        a1[10] = byte2f<2>(hi1);

        #pragma unroll
        for (int j = 0; j < 11; j++) {
            const ulonglong2* Wv =
                reinterpret_cast<const ulonglong2*>(&Ws[(et * 11 + j) * C_OUT]);
            unsigned long long av0, av1;
            asm("mov.b64 %0, {%1, %1};" : "=l"(av0) : "f"(a0[j]));
            asm("mov.b64 %0, {%1, %1};" : "=l"(av1) : "f"(a1[j]));
            #pragma unroll
            for (int q = 0; q < 8; q++) {
                ulonglong2 w = Wv[q];
                asm("fma.rn.f32x2 %0, %1, %2, %0;"
                    : "+l"(acc0[2 * q + 0]) : "l"(av0), "l"(w.x));
                asm("fma.rn.f32x2 %0, %1, %2, %0;"
                    : "+l"(acc0[2 * q + 1]) : "l"(av0), "l"(w.y));
                asm("fma.rn.f32x2 %0, %1, %2, %0;"
                    : "+l"(acc1[2 * q + 0]) : "l"(av1), "l"(w.x));
                asm("fma.rn.f32x2 %0, %1, %2, %0;"
                    : "+l"(acc1[2 * q + 1]) : "l"(av1), "l"(w.y));
            }
        }
    }

    const float* iv0 = &injs[bb.x * 33];
    const float* iv1 = &injs[bb.y * 33];
    float* op0 = out + (size_t)n0 * C_OUT;
    float* op1 = op0 + C_OUT;
    #pragma unroll
    for (int k = 0; k < 16; k += 2) {
        float l0, h0, l1, h1;
        asm("mov.b64 {%0, %1}, %2;" : "=f"(l0), "=f"(h0) : "l"(acc0[k]));
        asm("mov.b64 {%0, %1}, %2;" : "=f"(l1), "=f"(h1) : "l"(acc0[k + 1]));
        float4 o; o.x = l0 + iv0[2*k]; o.y = h0 + iv0[2*k+1];
        o.z = l1 + iv0[2*k+2]; o.w = h1 + iv0[2*k+3];
        __stcs(reinterpret_cast<float4*>(op0 + 2 * k), o);
        asm("mov.b64 {%0, %1}, %2;" : "=f"(l0), "=f"(h0) : "l"(acc1[k]));
        asm("mov.b64 {%0, %1}, %2;" : "=f"(l1), "=f"(h1) : "l"(acc1[k + 1]));
        float4 p; p.x = l0 + iv1[2*k]; p.y = h0 + iv1[2*k+1];
        p.z = l1 + iv1[2*k+2]; p.w = h1 + iv1[2*k+3];
        __stcs(reinterpret_cast<float4*>(op1 + 2 * k), p);
    }

    // Re-zero both nodes' accumulators (keep default policy: L2-resident).
    float4 z4 = make_float4(0.f, 0.f, 0.f, 0.f);
    #pragma unroll
    for (int i = 0; i < 2 * N_ETYPE; i++)
        *reinterpret_cast<float4*>(xp + i * 4) = z4;
    uint4 zu = make_uint4(0u, 0u, 0u, 0u);
    *reinterpret_cast<uint4*>(cp)      = zu;
    *reinterpret_cast<uint4*>(cp + 4)  = zu;
    *reinterpret_cast<uint4*>(cp + 8)  = zu;   // covers [8,12): node0 tail + node1 head
    *reinterpret_cast<uint4*>(cp + 12) = zu;
    *reinterpret_cast<uint4*>(cp + 16) = zu;
}

// ---------------------------------------------------------------------------
// Inputs (metadata order):
//  0 x [N,4] f32        1 t [8] f32          2 edge_index [2,E] i32
//  3 edge_type [E] i32  4 node_type [N] i32  5 batch_id [N] i32
//  6 W_conv [55,32] f32 7 W1 [128,512]       8 b1 [512]
//  9 W2 [512,512]      10 b2 [512]          11 W_temb [512,32]
// Output: [N,32] f32
// ---------------------------------------------------------------------------
extern "C" void kernel_launch(void* const* d_in, const int* in_sizes, int n_in,
                              void* d_out, int out_size) {
    const float* x        = (const float*)d_in[0];
    const float* t        = (const float*)d_in[1];
    const int*   ei       = (const int*)d_in[2];
    const int*   etype    = (const int*)d_in[3];
    const int*   ntype    = (const int*)d_in[4];
    const int*   batch_id = (const int*)d_in[5];
    const float* W_conv   = (const float*)d_in[6];
    const float* W1       = (const float*)d_in[7];
    const float* b1       = (const float*)d_in[8];
    const float* W2       = (const float*)d_in[9];
    const float* b2       = (const float*)d_in[10];
    const float* W_temb   = (const float*)d_in[11];
    float* out = (float*)d_out;

    const int E = in_sizes[3];
    const int N = in_sizes[4];
    const int edge_blocks = (E / 2 + 511) / 512;

    mega_kernel<<<72 + edge_blocks, 512>>>(t, W1, b1, W2, b2, W_temb,
                                           ei, etype, ntype, x, E);
    gemv_kernel<<<(N / 2 + 127) / 128, 128>>>(W_conv, batch_id, out, N);
}